// round 15
// baseline (speedup 1.0000x reference)
#include <cuda_runtime.h>
#include <cuda_fp16.h>
#include <cstdint>

#define HEAD   64
#define SEQ    4096
#define BATCH  4
#define SCALE_LOG2E 0.18033688011112042f   // 0.125 * log2(e)
#define QROWS  128
#define NQT    (SEQ / QROWS)     // 32
#define KTILE  64
#define CHUNK  8                 // kv tiles per CTA chunk (even!)
#define MAXCH  8
#define GBYTES 36864             // one 2-tile group: 2 x (K 9216 + V 9216)

// ---------------------------------------------------------------------------
// Scratch
// ---------------------------------------------------------------------------
__device__ __align__(16) __half g_qh [BATCH * SEQ * HEAD];   // [b][t][c] *SCALE*log2e
__device__ __align__(16) __half g_kh [BATCH * SEQ * HEAD];   // [b][t][c]
__device__ __align__(16) __half g_vTh[BATCH * HEAD * SEQ];   // [b][c][t]
__device__ __align__(16) float g_Opart[BATCH * NQT * MAXCH * QROWS * HEAD];
__device__ __align__(16) float g_lpart[BATCH * NQT * MAXCH * QROWS];

// ---------------------------------------------------------------------------
// PTX helpers (generic sm_80+ only — target is plain sm_103)
// ---------------------------------------------------------------------------
__device__ __forceinline__ uint32_t smem_u32(const void* p) {
    uint32_t a;
    asm("{ .reg .u64 t; cvta.to.shared.u64 t, %1; cvt.u32.u64 %0, t; }"
        : "=r"(a) : "l"(p));
    return a;
}

#define LDSM4(r, addr) \
    asm volatile("ldmatrix.sync.aligned.m8n8.x4.shared.b16 {%0,%1,%2,%3}, [%4];" \
        : "=r"((r)[0]), "=r"((r)[1]), "=r"((r)[2]), "=r"((r)[3]) : "r"(addr))

#define MMA16816F16(d, a, b0, b1) \
    asm volatile("mma.sync.aligned.m16n8k16.row.col.f32.f16.f16.f32 " \
        "{%0,%1,%2,%3}, {%4,%5,%6,%7}, {%8,%9}, {%0,%1,%2,%3};" \
        : "+f"((d)[0]), "+f"((d)[1]), "+f"((d)[2]), "+f"((d)[3]) \
        : "r"((a)[0]), "r"((a)[1]), "r"((a)[2]), "r"((a)[3]), "r"(b0), "r"(b1))

#define CP_ASYNC16(smaddr, gptr) \
    asm volatile("cp.async.cg.shared.global [%0], [%1], 16;" \
        :: "r"(smaddr), "l"(gptr) : "memory")
#define CP_COMMIT() asm volatile("cp.async.commit_group;" ::: "memory")
#define CP_WAIT0()  asm volatile("cp.async.wait_group 0;"  ::: "memory")

__device__ __forceinline__ uint32_t pack_h2(float a, float b) {
    __half2 h = __floats2half2_rn(a, b);
    return *(uint32_t*)&h;
}
__device__ __forceinline__ float ex2f(float x) {
    float y; asm("ex2.approx.ftz.f32 %0, %1;" : "=f"(y) : "f"(x)); return y;
}

// ---------------------------------------------------------------------------
// Kernel 1: QKV projection on tensor cores (fp16 hi/lo 3-term, fp32 accum).
// ---------------------------------------------------------------------------
__global__ __launch_bounds__(256) void qkv_proj_kernel(
    const float* __restrict__ x,  const float* __restrict__ Wk,
    const float* __restrict__ Wq, const float* __restrict__ Wv)
{
    __shared__ __align__(16) uint8_t smx[2][64 * 144];   // x hi, lo
    __shared__ __align__(16) uint8_t smw[2][64 * 144];   // W hi, lo

    const int tid  = threadIdx.x;
    const int w    = tid >> 5;
    const int lane = tid & 31;
    const int row0 = blockIdx.x * 64;
    const int m    = blockIdx.y;

    const float* W = (m == 0) ? Wq : (m == 1) ? Wk : Wv;

    for (int i = tid; i < 64 * 16; i += 256) {
        int r = i >> 4, c4 = (i & 15) << 2;
        float4 v = *(const float4*)&x[(size_t)(row0 + r) * HEAD + c4];
        __half h0 = __float2half_rn(v.x), h1 = __float2half_rn(v.y);
        __half h2 = __float2half_rn(v.z), h3 = __float2half_rn(v.w);
        uint32_t off = (uint32_t)r * 144 + (uint32_t)c4 * 2;
        __half2 hh;
        hh.x = h0; hh.y = h1; *(uint32_t*)&smx[0][off]     = *(uint32_t*)&hh;
        hh.x = h2; hh.y = h3; *(uint32_t*)&smx[0][off + 4] = *(uint32_t*)&hh;
        hh.x = __float2half_rn(v.x - __half2float(h0));
        hh.y = __float2half_rn(v.y - __half2float(h1));
        *(uint32_t*)&smx[1][off]     = *(uint32_t*)&hh;
        hh.x = __float2half_rn(v.z - __half2float(h2));
        hh.y = __float2half_rn(v.w - __half2float(h3));
        *(uint32_t*)&smx[1][off + 4] = *(uint32_t*)&hh;
    }
    for (int i = tid; i < 64 * 16; i += 256) {
        int r = i >> 4, c4 = (i & 15) << 2;
        float4 v = *(const float4*)&W[(size_t)r * HEAD + c4];
        __half h0 = __float2half_rn(v.x), h1 = __float2half_rn(v.y);
        __half h2 = __float2half_rn(v.z), h3 = __float2half_rn(v.w);
        uint32_t off = (uint32_t)r * 144 + (uint32_t)c4 * 2;
        __half2 hh;
        hh.x = h0; hh.y = h1; *(uint32_t*)&smw[0][off]     = *(uint32_t*)&hh;
        hh.x = h2; hh.y = h3; *(uint32_t*)&smw[0][off + 4] = *(uint32_t*)&hh;
        hh.x = __float2half_rn(v.x - __half2float(h0));
        hh.y = __float2half_rn(v.y - __half2float(h1));
        *(uint32_t*)&smw[1][off]     = *(uint32_t*)&hh;
        hh.x = __float2half_rn(v.z - __half2float(h2));
        hh.y = __float2half_rn(v.w - __half2float(h3));
        *(uint32_t*)&smw[1][off + 4] = *(uint32_t*)&hh;
    }
    __syncthreads();

    uint32_t xh[4][4], xl[4][4];
    {
        const uint32_t base = (uint32_t)(16 * (w & 3) + (lane & 15)) * 144 + ((uint32_t)(lane >> 4) << 4);
        const uint32_t rah = smem_u32(&smx[0][0]) + base;
        const uint32_t ral = smem_u32(&smx[1][0]) + base;
        #pragma unroll
        for (int ks = 0; ks < 4; ks++) {
            LDSM4(xh[ks], rah + ks * 32);
            LDSM4(xl[ks], ral + ks * 32);
        }
    }

    float s[16];
    #pragma unroll
    for (int i = 0; i < 16; i++) s[i] = 0.f;

    #pragma unroll
    for (int ks = 0; ks < 4; ks++) {
        #pragma unroll
        for (int pr = 0; pr < 2; pr++) {
            const uint32_t a = smem_u32(&smw[0][0]) +
                (uint32_t)(32 * (w >> 2) + pr * 16 + (lane & 15)) * 144 +
                ((uint32_t)(lane >> 4) << 4) + ks * 32;
            uint32_t wh4[4], wl4[4];
            LDSM4(wh4, a);
            LDSM4(wl4, a + 9216);
            float* s0 = s + (2 * pr) * 4;
            float* s1 = s + (2 * pr + 1) * 4;
            MMA16816F16(s0, xh[ks], wh4[0], wh4[2]);
            MMA16816F16(s0, xh[ks], wl4[0], wl4[2]);
            MMA16816F16(s0, xl[ks], wh4[0], wh4[2]);
            MMA16816F16(s1, xh[ks], wh4[1], wh4[3]);
            MMA16816F16(s1, xh[ks], wl4[1], wl4[3]);
            MMA16816F16(s1, xl[ks], wh4[1], wh4[3]);
        }
    }

    const int b    = row0 / SEQ;
    const int r0   = 16 * (w & 3) + (lane >> 2);
    const int g0   = row0 + r0;
    const int g1   = g0 + 8;
    const int tv0  = g0 - b * SEQ;
    const int tv1  = tv0 + 8;
    const float sc = (m == 0) ? SCALE_LOG2E : 1.0f;

    #pragma unroll
    for (int nt = 0; nt < 4; nt++) {
        const int col = 32 * (w >> 2) + nt * 8 + 2 * (lane & 3);
        float a0 = s[nt * 4]     * sc, a1 = s[nt * 4 + 1] * sc;
        float a2 = s[nt * 4 + 2] * sc, a3 = s[nt * 4 + 3] * sc;
        if (m < 2) {
            __half* dst = (m == 0) ? g_qh : g_kh;
            *(uint32_t*)&dst[(size_t)g0 * HEAD + col] = pack_h2(a0, a1);
            *(uint32_t*)&dst[(size_t)g1 * HEAD + col] = pack_h2(a2, a3);
        } else {
            g_vTh[((size_t)b * HEAD + col)     * SEQ + tv0] = __float2half_rn(a0);
            g_vTh[((size_t)b * HEAD + col + 1) * SEQ + tv0] = __float2half_rn(a1);
            g_vTh[((size_t)b * HEAD + col)     * SEQ + tv1] = __float2half_rn(a2);
            g_vTh[((size_t)b * HEAD + col + 1) * SEQ + tv1] = __float2half_rn(a3);
        }
    }
}

// ---------------------------------------------------------------------------
// Kernel 2: fp16 mma.sync causal attention. cp.async double-buffered GROUPS
// of 2 KV tiles -> one __syncthreads per 2 tiles, copies hidden by compute.
// Dynamic smem: 2 groups x 36864B = 73728B. occ 2 (147KB/SM).
// ---------------------------------------------------------------------------
__global__ __launch_bounds__(256, 2) void attn_kernel()
{
    extern __shared__ __align__(16) uint8_t smB[];

    const int tid  = threadIdx.x;
    const int w    = tid >> 5;
    const int lane = tid & 31;

    const int bx = blockIdx.x;
    const int b  = bx & 3;
    const int qt = (NQT - 1) - ((bx >> 2) & 31);  // heavy tiles first
    const int ch = bx >> 7;

    const int ntiles = 2 * qt + 2;                // always even
    const int t0 = ch * CHUNK;                    // even
    const int t1 = (t0 + CHUNK < ntiles) ? (t0 + CHUNK) : ntiles;
    if (t0 >= t1) return;
    const int ngroups = (t1 - t0) >> 1;

    const uint32_t smb = smem_u32(smB);

    const __half* kbase = g_kh  + (size_t)b * SEQ * HEAD;
    const __half* vbase = g_vTh + (size_t)b * HEAD * SEQ;

    const int e0r = tid >> 3,          e0c = tid & 7;
    const int e1r = (tid + 256) >> 3,  e1c = tid & 7;

    // issue one 2-tile group (8 x 16B cp.async per thread), single commit
    auto issue_group = [&](uint32_t gbase, int tfirst) {
        #pragma unroll
        for (int slot = 0; slot < 2; slot++) {
            const int tl = tfirst + slot;
            const __half* kp = kbase + (size_t)tl * KTILE * HEAD;
            const __half* vp = vbase + (size_t)tl * KTILE;
            const uint32_t kb = smb + gbase + (uint32_t)slot * 18432;
            CP_ASYNC16(kb + e0r * 144 + e0c * 16,        kp + (size_t)e0r * HEAD + e0c * 8);
            CP_ASYNC16(kb + e1r * 144 + e1c * 16,        kp + (size_t)e1r * HEAD + e1c * 8);
            CP_ASYNC16(kb + 9216 + e0r * 144 + e0c * 16, vp + (size_t)e0r * SEQ  + e0c * 8);
            CP_ASYNC16(kb + 9216 + e1r * 144 + e1c * 16, vp + (size_t)e1r * SEQ  + e1c * 8);
        }
        CP_COMMIT();
    };

    // ---- prologue: start group 0 into buf0; stage Q into buf1 area ----
    issue_group(0, t0);
    {
        const __half* qh = g_qh + ((size_t)b * SEQ + (size_t)qt * QROWS) * HEAD;
        for (int i = tid; i < 128 * 8; i += 256) {
            int r = i >> 3, c = i & 7;
            *(uint4*)(smB + GBYTES + r * 144 + c * 16) = *(const uint4*)(qh + r * HEAD + c * 8);
        }
    }
    __syncthreads();

    uint32_t qF[4][4];
    {
        const uint32_t ra = smb + GBYTES + (uint32_t)(w * 16 + (lane & 15)) * 144 + ((lane >> 4) << 4);
        #pragma unroll
        for (int ks = 0; ks < 4; ks++) LDSM4(qF[ks], ra + ks * 32);
    }

    float o[32];
    #pragma unroll
    for (int i = 0; i < 32; i++) o[i] = 0.f;
    float l0 = 0.f, l1 = 0.f;

    const int row_in0 = w * 16 + (lane >> 2);
    const int grow0 = qt * QROWS + row_in0;
    const int grow1 = grow0 + 8;
    const uint32_t lrow  = (uint32_t)(lane & 15) * 144;
    const uint32_t lhalf = ((uint32_t)(lane >> 4)) << 4;

    for (int g = 0; g < ngroups; g++) {
        CP_WAIT0();          // this thread's group g copies done
        __syncthreads();     // all threads' done; prev buffer free (incl. Q LDSM at g=0)

        if (g + 1 < ngroups)
            issue_group((uint32_t)((g + 1) & 1) * GBYTES, t0 + 2 * (g + 1));

        const uint32_t gb = (uint32_t)(g & 1) * GBYTES;

        #pragma unroll
        for (int slot = 0; slot < 2; slot++) {
            const int tl = t0 + 2 * g + slot;
            const uint32_t tb = gb + (uint32_t)slot * 18432;

            // ---- S = Q K^T ----
            float s[32];
            #pragma unroll
            for (int i = 0; i < 32; i++) s[i] = 0.f;

            #pragma unroll
            for (int ks = 0; ks < 4; ks++) {
                #pragma unroll
                for (int pr = 0; pr < 4; pr++) {
                    const uint32_t a = smb + tb + (uint32_t)(pr * 16) * 144 + lrow + lhalf + ks * 32;
                    uint32_t k4[4];
                    LDSM4(k4, a);
                    MMA16816F16(s + (2 * pr) * 4,     qF[ks], k4[0], k4[2]);
                    MMA16816F16(s + (2 * pr + 1) * 4, qF[ks], k4[1], k4[3]);
                }
            }

            // ---- softmax via ex2 ----
            const bool diag = (tl >= 2 * qt);
            uint32_t pF[4][4];
            #pragma unroll
            for (int nt = 0; nt < 8; nt++) {
                const float* sp = s + nt * 4;
                float p0, p1, p2, p3;
                if (diag) {
                    const int colb = tl * KTILE + nt * 8 + 2 * (lane & 3);
                    p0 = (colb     <= grow0) ? ex2f(sp[0]) : 0.f;
                    p1 = (colb + 1 <= grow0) ? ex2f(sp[1]) : 0.f;
                    p2 = (colb     <= grow1) ? ex2f(sp[2]) : 0.f;
                    p3 = (colb + 1 <= grow1) ? ex2f(sp[3]) : 0.f;
                } else {
                    p0 = ex2f(sp[0]); p1 = ex2f(sp[1]);
                    p2 = ex2f(sp[2]); p3 = ex2f(sp[3]);
                }
                l0 += p0 + p1;
                l1 += p2 + p3;
                const int ks  = nt >> 1;
                const int sel = (nt & 1) << 1;
                pF[ks][sel]     = pack_h2(p0, p1);
                pF[ks][sel + 1] = pack_h2(p2, p3);
            }

            // ---- O += P V ----
            #pragma unroll
            for (int ks = 0; ks < 4; ks++) {
                #pragma unroll
                for (int pr = 0; pr < 4; pr++) {
                    const uint32_t a = smb + tb + 9216 + (uint32_t)(pr * 16) * 144 + lrow + lhalf + ks * 32;
                    uint32_t v4[4];
                    LDSM4(v4, a);
                    MMA16816F16(o + (2 * pr) * 4,     pF[ks], v4[0], v4[2]);
                    MMA16816F16(o + (2 * pr + 1) * 4, pF[ks], v4[1], v4[3]);
                }
            }
        }
    }

    l0 += __shfl_xor_sync(0xffffffffu, l0, 1);
    l0 += __shfl_xor_sync(0xffffffffu, l0, 2);
    l1 += __shfl_xor_sync(0xffffffffu, l1, 1);
    l1 += __shfl_xor_sync(0xffffffffu, l1, 2);

    const size_t pb = ((size_t)(b * NQT + qt) * MAXCH + ch) * QROWS;
    const int c0 = 2 * (lane & 3);
    #pragma unroll
    for (int nt = 0; nt < 8; nt++) {
        float2 va = make_float2(o[nt * 4],     o[nt * 4 + 1]);
        float2 vb = make_float2(o[nt * 4 + 2], o[nt * 4 + 3]);
        *(float2*)&g_Opart[(pb + row_in0)     * HEAD + nt * 8 + c0] = va;
        *(float2*)&g_Opart[(pb + row_in0 + 8) * HEAD + nt * 8 + c0] = vb;
    }
    if ((lane & 3) == 0) {
        g_lpart[pb + row_in0]     = l0;
        g_lpart[pb + row_in0 + 8] = l1;
    }
}

// ---------------------------------------------------------------------------
// Kernel 3: combine split-KV partials (pure additive) + normalize.
// ---------------------------------------------------------------------------
__global__ __launch_bounds__(QROWS) void combine_kernel(float* __restrict__ out)
{
    const int b  = blockIdx.x & 3;
    const int qt = blockIdx.x >> 2;
    const int r  = threadIdx.x;
    const int nch = (2 * qt + 2 + CHUNK - 1) / CHUNK;

    float acc[HEAD];
    #pragma unroll
    for (int i = 0; i < HEAD; i++) acc[i] = 0.0f;
    float l = 0.0f;

    for (int ch = 0; ch < nch; ch++) {
        const size_t base = (((size_t)(b * NQT + qt) * MAXCH + ch) * QROWS + r) * HEAD;
        const float4* op = (const float4*)(g_Opart + base);
        #pragma unroll
        for (int i = 0; i < 16; i++) {
            float4 v = op[i];
            acc[4 * i] += v.x; acc[4 * i + 1] += v.y;
            acc[4 * i + 2] += v.z; acc[4 * i + 3] += v.w;
        }
        l += g_lpart[((size_t)(b * NQT + qt) * MAXCH + ch) * QROWS + r];
    }

    const float inv = 1.0f / l;
    float4* dst = (float4*)(out + ((size_t)b * SEQ + (size_t)qt * QROWS + r) * HEAD);
    #pragma unroll
    for (int i = 0; i < 16; i++) {
        dst[i] = make_float4(acc[4 * i] * inv, acc[4 * i + 1] * inv,
                             acc[4 * i + 2] * inv, acc[4 * i + 3] * inv);
    }
}

// ---------------------------------------------------------------------------
extern "C" void kernel_launch(void* const* d_in, const int* in_sizes, int n_in,
                              void* d_out, int out_size)
{
    const float* x  = (const float*)d_in[0];
    const float* Wk = (const float*)d_in[1];
    const float* Wq = (const float*)d_in[2];
    const float* Wv = (const float*)d_in[3];
    float* out = (float*)d_out;

    qkv_proj_kernel<<<dim3(BATCH * SEQ / 64, 3), 256>>>(x, Wk, Wq, Wv);

    cudaFuncSetAttribute(attn_kernel,
                         cudaFuncAttributeMaxDynamicSharedMemorySize, 2 * GBYTES);
    attn_kernel<<<BATCH * NQT * MAXCH, 256, 2 * GBYTES>>>();

    combine_kernel<<<BATCH * NQT, QROWS>>>(out);
}

// round 16
// speedup vs baseline: 1.5166x; 1.5166x over previous
#include <cuda_runtime.h>
#include <cuda_fp16.h>
#include <cstdint>

#define HEAD   64
#define SEQ    4096
#define BATCH  4
#define SCALE_LOG2E 0.18033688011112042f   // 0.125 * log2(e)
#define QROWS  128
#define NQT    (SEQ / QROWS)     // 32
#define KTILE  64
#define CHUNK  8                 // kv tiles per CTA chunk
#define MAXCH  8

// ---------------------------------------------------------------------------
// Scratch
// ---------------------------------------------------------------------------
__device__ __align__(16) __half g_qh [BATCH * SEQ * HEAD];   // [b][t][c] *SCALE*log2e
__device__ __align__(16) __half g_kh [BATCH * SEQ * HEAD];   // [b][t][c]
__device__ __align__(16) __half g_vTh[BATCH * HEAD * SEQ];   // [b][c][t]
__device__ __align__(16) float g_Opart[BATCH * NQT * MAXCH * QROWS * HEAD];
__device__ __align__(16) float g_lpart[BATCH * NQT * MAXCH * QROWS];

// ---------------------------------------------------------------------------
// PTX helpers (generic sm_80+ only — target is plain sm_103)
// ---------------------------------------------------------------------------
__device__ __forceinline__ uint32_t smem_u32(const void* p) {
    uint32_t a;
    asm("{ .reg .u64 t; cvta.to.shared.u64 t, %1; cvt.u32.u64 %0, t; }"
        : "=r"(a) : "l"(p));
    return a;
}

#define LDSM4(r, addr) \
    asm volatile("ldmatrix.sync.aligned.m8n8.x4.shared.b16 {%0,%1,%2,%3}, [%4];" \
        : "=r"((r)[0]), "=r"((r)[1]), "=r"((r)[2]), "=r"((r)[3]) : "r"(addr))

#define MMA16816F16(d, a, b0, b1) \
    asm volatile("mma.sync.aligned.m16n8k16.row.col.f32.f16.f16.f32 " \
        "{%0,%1,%2,%3}, {%4,%5,%6,%7}, {%8,%9}, {%0,%1,%2,%3};" \
        : "+f"((d)[0]), "+f"((d)[1]), "+f"((d)[2]), "+f"((d)[3]) \
        : "r"((a)[0]), "r"((a)[1]), "r"((a)[2]), "r"((a)[3]), "r"(b0), "r"(b1))

#define CP_ASYNC16(smaddr, gptr) \
    asm volatile("cp.async.cg.shared.global [%0], [%1], 16;" \
        :: "r"(smaddr), "l"(gptr) : "memory")
#define CP_COMMIT() asm volatile("cp.async.commit_group;" ::: "memory")
#define CP_WAIT0()  asm volatile("cp.async.wait_group 0;"  ::: "memory")

__device__ __forceinline__ uint32_t pack_h2(float a, float b) {
    __half2 h = __floats2half2_rn(a, b);
    return *(uint32_t*)&h;
}
__device__ __forceinline__ float ex2f(float x) {
    float y; asm("ex2.approx.ftz.f32 %0, %1;" : "=f"(y) : "f"(x)); return y;
}

// ---------------------------------------------------------------------------
// Kernel 1: QKV projection on tensor cores (fp16 hi/lo 3-term, fp32 accum).
// (unchanged from R14: measured 11.97us)
// ---------------------------------------------------------------------------
__global__ __launch_bounds__(256) void qkv_proj_kernel(
    const float* __restrict__ x,  const float* __restrict__ Wk,
    const float* __restrict__ Wq, const float* __restrict__ Wv)
{
    __shared__ __align__(16) uint8_t smx[2][64 * 144];   // x hi, lo
    __shared__ __align__(16) uint8_t smw[2][64 * 144];   // W hi, lo

    const int tid  = threadIdx.x;
    const int w    = tid >> 5;
    const int lane = tid & 31;
    const int row0 = blockIdx.x * 64;
    const int m    = blockIdx.y;

    const float* W = (m == 0) ? Wq : (m == 1) ? Wk : Wv;

    for (int i = tid; i < 64 * 16; i += 256) {
        int r = i >> 4, c4 = (i & 15) << 2;
        float4 v = *(const float4*)&x[(size_t)(row0 + r) * HEAD + c4];
        __half h0 = __float2half_rn(v.x), h1 = __float2half_rn(v.y);
        __half h2 = __float2half_rn(v.z), h3 = __float2half_rn(v.w);
        uint32_t off = (uint32_t)r * 144 + (uint32_t)c4 * 2;
        __half2 hh;
        hh.x = h0; hh.y = h1; *(uint32_t*)&smx[0][off]     = *(uint32_t*)&hh;
        hh.x = h2; hh.y = h3; *(uint32_t*)&smx[0][off + 4] = *(uint32_t*)&hh;
        hh.x = __float2half_rn(v.x - __half2float(h0));
        hh.y = __float2half_rn(v.y - __half2float(h1));
        *(uint32_t*)&smx[1][off]     = *(uint32_t*)&hh;
        hh.x = __float2half_rn(v.z - __half2float(h2));
        hh.y = __float2half_rn(v.w - __half2float(h3));
        *(uint32_t*)&smx[1][off + 4] = *(uint32_t*)&hh;
    }
    for (int i = tid; i < 64 * 16; i += 256) {
        int r = i >> 4, c4 = (i & 15) << 2;
        float4 v = *(const float4*)&W[(size_t)r * HEAD + c4];
        __half h0 = __float2half_rn(v.x), h1 = __float2half_rn(v.y);
        __half h2 = __float2half_rn(v.z), h3 = __float2half_rn(v.w);
        uint32_t off = (uint32_t)r * 144 + (uint32_t)c4 * 2;
        __half2 hh;
        hh.x = h0; hh.y = h1; *(uint32_t*)&smw[0][off]     = *(uint32_t*)&hh;
        hh.x = h2; hh.y = h3; *(uint32_t*)&smw[0][off + 4] = *(uint32_t*)&hh;
        hh.x = __float2half_rn(v.x - __half2float(h0));
        hh.y = __float2half_rn(v.y - __half2float(h1));
        *(uint32_t*)&smw[1][off]     = *(uint32_t*)&hh;
        hh.x = __float2half_rn(v.z - __half2float(h2));
        hh.y = __float2half_rn(v.w - __half2float(h3));
        *(uint32_t*)&smw[1][off + 4] = *(uint32_t*)&hh;
    }
    __syncthreads();

    uint32_t xh[4][4], xl[4][4];
    {
        const uint32_t base = (uint32_t)(16 * (w & 3) + (lane & 15)) * 144 + ((uint32_t)(lane >> 4) << 4);
        const uint32_t rah = smem_u32(&smx[0][0]) + base;
        const uint32_t ral = smem_u32(&smx[1][0]) + base;
        #pragma unroll
        for (int ks = 0; ks < 4; ks++) {
            LDSM4(xh[ks], rah + ks * 32);
            LDSM4(xl[ks], ral + ks * 32);
        }
    }

    float s[16];
    #pragma unroll
    for (int i = 0; i < 16; i++) s[i] = 0.f;

    #pragma unroll
    for (int ks = 0; ks < 4; ks++) {
        #pragma unroll
        for (int pr = 0; pr < 2; pr++) {
            const uint32_t a = smem_u32(&smw[0][0]) +
                (uint32_t)(32 * (w >> 2) + pr * 16 + (lane & 15)) * 144 +
                ((uint32_t)(lane >> 4) << 4) + ks * 32;
            uint32_t wh4[4], wl4[4];
            LDSM4(wh4, a);
            LDSM4(wl4, a + 9216);
            float* s0 = s + (2 * pr) * 4;
            float* s1 = s + (2 * pr + 1) * 4;
            MMA16816F16(s0, xh[ks], wh4[0], wh4[2]);
            MMA16816F16(s0, xh[ks], wl4[0], wl4[2]);
            MMA16816F16(s0, xl[ks], wh4[0], wh4[2]);
            MMA16816F16(s1, xh[ks], wh4[1], wh4[3]);
            MMA16816F16(s1, xh[ks], wl4[1], wl4[3]);
            MMA16816F16(s1, xl[ks], wh4[1], wh4[3]);
        }
    }

    const int b    = row0 / SEQ;
    const int r0   = 16 * (w & 3) + (lane >> 2);
    const int g0   = row0 + r0;
    const int g1   = g0 + 8;
    const int tv0  = g0 - b * SEQ;
    const int tv1  = tv0 + 8;
    const float sc = (m == 0) ? SCALE_LOG2E : 1.0f;

    #pragma unroll
    for (int nt = 0; nt < 4; nt++) {
        const int col = 32 * (w >> 2) + nt * 8 + 2 * (lane & 3);
        float a0 = s[nt * 4]     * sc, a1 = s[nt * 4 + 1] * sc;
        float a2 = s[nt * 4 + 2] * sc, a3 = s[nt * 4 + 3] * sc;
        if (m < 2) {
            __half* dst = (m == 0) ? g_qh : g_kh;
            *(uint32_t*)&dst[(size_t)g0 * HEAD + col] = pack_h2(a0, a1);
            *(uint32_t*)&dst[(size_t)g1 * HEAD + col] = pack_h2(a2, a3);
        } else {
            g_vTh[((size_t)b * HEAD + col)     * SEQ + tv0] = __float2half_rn(a0);
            g_vTh[((size_t)b * HEAD + col + 1) * SEQ + tv0] = __float2half_rn(a1);
            g_vTh[((size_t)b * HEAD + col)     * SEQ + tv1] = __float2half_rn(a2);
            g_vTh[((size_t)b * HEAD + col + 1) * SEQ + tv1] = __float2half_rn(a3);
        }
    }
}

// ---------------------------------------------------------------------------
// Kernel 2: fp16 mma.sync causal attention — R14 structure exactly (static
// 36.9KB smem, 1 tile/buffer, 1 sync/iter, same compute body), with the
// register prefetch replaced by cp.async (frees ~16 regs, drops tail STS).
// ---------------------------------------------------------------------------
__global__ __launch_bounds__(256, 2) void attn_kernel()
{
    __shared__ __align__(16) uint8_t smB[2 * 18432];

    const int tid  = threadIdx.x;
    const int w    = tid >> 5;
    const int lane = tid & 31;

    const int bx = blockIdx.x;
    const int b  = bx & 3;
    const int qt = (NQT - 1) - ((bx >> 2) & 31);  // heavy tiles first
    const int ch = bx >> 7;

    const int ntiles = 2 * qt + 2;
    const int t0 = ch * CHUNK;
    const int t1 = (t0 + CHUNK < ntiles) ? (t0 + CHUNK) : ntiles;
    if (t0 >= t1) return;

    const uint32_t smb = smem_u32(smB);

    const __half* kbase = g_kh  + (size_t)b * SEQ * HEAD;
    const __half* vbase = g_vTh + (size_t)b * HEAD * SEQ;

    const int e0r = tid >> 3,          e0c = tid & 7;
    const int e1r = (tid + 256) >> 3,  e1c = tid & 7;

    // issue one KV tile (4 x 16B cp.async per thread), single commit
    auto issue_tile = [&](uint32_t tb, int tl) {
        const __half* kp = kbase + (size_t)tl * KTILE * HEAD;
        const __half* vp = vbase + (size_t)tl * KTILE;
        CP_ASYNC16(smb + tb + e0r * 144 + e0c * 16,        kp + (size_t)e0r * HEAD + e0c * 8);
        CP_ASYNC16(smb + tb + e1r * 144 + e1c * 16,        kp + (size_t)e1r * HEAD + e1c * 8);
        CP_ASYNC16(smb + tb + 9216 + e0r * 144 + e0c * 16, vp + (size_t)e0r * SEQ  + e0c * 8);
        CP_ASYNC16(smb + tb + 9216 + e1r * 144 + e1c * 16, vp + (size_t)e1r * SEQ  + e1c * 8);
        CP_COMMIT();
    };

    // ---- prologue: start tile t0 into buf0; stage Q into buf1 area ----
    issue_tile(0, t0);
    {
        const __half* qh = g_qh + ((size_t)b * SEQ + (size_t)qt * QROWS) * HEAD;
        for (int i = tid; i < 128 * 8; i += 256) {
            int r = i >> 3, c = i & 7;
            *(uint4*)(smB + 18432 + r * 144 + c * 16) = *(const uint4*)(qh + r * HEAD + c * 8);
        }
    }
    __syncthreads();

    uint32_t qF[4][4];
    {
        const uint32_t ra = smb + 18432 + (uint32_t)(w * 16 + (lane & 15)) * 144 + ((lane >> 4) << 4);
        #pragma unroll
        for (int ks = 0; ks < 4; ks++) LDSM4(qF[ks], ra + ks * 32);
    }

    float o[32];
    #pragma unroll
    for (int i = 0; i < 32; i++) o[i] = 0.f;
    float l0 = 0.f, l1 = 0.f;

    const int row_in0 = w * 16 + (lane >> 2);
    const int grow0 = qt * QROWS + row_in0;
    const int grow1 = grow0 + 8;
    const uint32_t lrow  = (uint32_t)(lane & 15) * 144;
    const uint32_t lhalf = ((uint32_t)(lane >> 4)) << 4;

    for (int tl = t0; tl < t1; tl++) {
        const uint32_t cur = (uint32_t)((tl - t0) & 1) * 18432;
        const uint32_t nxt = cur ^ 18432;

        CP_WAIT0();          // this thread's copies for tile tl complete
        __syncthreads();     // all threads' copies visible; buf[nxt] readers done
                             // (at tl==t0 this also covers every warp's Q LDSM)

        if (tl + 1 < t1) issue_tile(nxt, tl + 1);   // copy hidden under compute

        // ---- S = Q K^T ----
        float s[32];
        #pragma unroll
        for (int i = 0; i < 32; i++) s[i] = 0.f;

        #pragma unroll
        for (int ks = 0; ks < 4; ks++) {
            #pragma unroll
            for (int pr = 0; pr < 4; pr++) {
                const uint32_t a = smb + cur + (uint32_t)(pr * 16) * 144 + lrow + lhalf + ks * 32;
                uint32_t k4[4];
                LDSM4(k4, a);
                MMA16816F16(s + (2 * pr) * 4,     qF[ks], k4[0], k4[2]);
                MMA16816F16(s + (2 * pr + 1) * 4, qF[ks], k4[1], k4[3]);
            }
        }

        // ---- softmax via ex2 (S carries log2e) ----
        const bool diag = (tl >= 2 * qt);
        uint32_t pF[4][4];
        #pragma unroll
        for (int nt = 0; nt < 8; nt++) {
            const float* sp = s + nt * 4;
            float p0, p1, p2, p3;
            if (diag) {
                const int colb = tl * KTILE + nt * 8 + 2 * (lane & 3);
                p0 = (colb     <= grow0) ? ex2f(sp[0]) : 0.f;
                p1 = (colb + 1 <= grow0) ? ex2f(sp[1]) : 0.f;
                p2 = (colb     <= grow1) ? ex2f(sp[2]) : 0.f;
                p3 = (colb + 1 <= grow1) ? ex2f(sp[3]) : 0.f;
            } else {
                p0 = ex2f(sp[0]); p1 = ex2f(sp[1]);
                p2 = ex2f(sp[2]); p3 = ex2f(sp[3]);
            }
            l0 += p0 + p1;
            l1 += p2 + p3;
            const int ks  = nt >> 1;
            const int sel = (nt & 1) << 1;
            pF[ks][sel]     = pack_h2(p0, p1);
            pF[ks][sel + 1] = pack_h2(p2, p3);
        }

        // ---- O += P V ----
        #pragma unroll
        for (int ks = 0; ks < 4; ks++) {
            #pragma unroll
            for (int pr = 0; pr < 4; pr++) {
                const uint32_t a = smb + cur + 9216 + (uint32_t)(pr * 16) * 144 + lrow + lhalf + ks * 32;
                uint32_t v4[4];
                LDSM4(v4, a);
                MMA16816F16(o + (2 * pr) * 4,     pF[ks], v4[0], v4[2]);
                MMA16816F16(o + (2 * pr + 1) * 4, pF[ks], v4[1], v4[3]);
            }
        }
    }

    l0 += __shfl_xor_sync(0xffffffffu, l0, 1);
    l0 += __shfl_xor_sync(0xffffffffu, l0, 2);
    l1 += __shfl_xor_sync(0xffffffffu, l1, 1);
    l1 += __shfl_xor_sync(0xffffffffu, l1, 2);

    const size_t pb = ((size_t)(b * NQT + qt) * MAXCH + ch) * QROWS;
    const int c0 = 2 * (lane & 3);
    #pragma unroll
    for (int nt = 0; nt < 8; nt++) {
        float2 va = make_float2(o[nt * 4],     o[nt * 4 + 1]);
        float2 vb = make_float2(o[nt * 4 + 2], o[nt * 4 + 3]);
        *(float2*)&g_Opart[(pb + row_in0)     * HEAD + nt * 8 + c0] = va;
        *(float2*)&g_Opart[(pb + row_in0 + 8) * HEAD + nt * 8 + c0] = vb;
    }
    if ((lane & 3) == 0) {
        g_lpart[pb + row_in0]     = l0;
        g_lpart[pb + row_in0 + 8] = l1;
    }
}

// ---------------------------------------------------------------------------
// Kernel 3: combine split-KV partials (pure additive) + normalize.
// ---------------------------------------------------------------------------
__global__ __launch_bounds__(QROWS) void combine_kernel(float* __restrict__ out)
{
    const int b  = blockIdx.x & 3;
    const int qt = blockIdx.x >> 2;
    const int r  = threadIdx.x;
    const int nch = (2 * qt + 2 + CHUNK - 1) / CHUNK;

    float acc[HEAD];
    #pragma unroll
    for (int i = 0; i < HEAD; i++) acc[i] = 0.0f;
    float l = 0.0f;

    for (int ch = 0; ch < nch; ch++) {
        const size_t base = (((size_t)(b * NQT + qt) * MAXCH + ch) * QROWS + r) * HEAD;
        const float4* op = (const float4*)(g_Opart + base);
        #pragma unroll
        for (int i = 0; i < 16; i++) {
            float4 v = op[i];
            acc[4 * i] += v.x; acc[4 * i + 1] += v.y;
            acc[4 * i + 2] += v.z; acc[4 * i + 3] += v.w;
        }
        l += g_lpart[((size_t)(b * NQT + qt) * MAXCH + ch) * QROWS + r];
    }

    const float inv = 1.0f / l;
    float4* dst = (float4*)(out + ((size_t)b * SEQ + (size_t)qt * QROWS + r) * HEAD);
    #pragma unroll
    for (int i = 0; i < 16; i++) {
        dst[i] = make_float4(acc[4 * i] * inv, acc[4 * i + 1] * inv,
                             acc[4 * i + 2] * inv, acc[4 * i + 3] * inv);
    }
}

// ---------------------------------------------------------------------------
extern "C" void kernel_launch(void* const* d_in, const int* in_sizes, int n_in,
                              void* d_out, int out_size)
{
    const float* x  = (const float*)d_in[0];
    const float* Wk = (const float*)d_in[1];
    const float* Wq = (const float*)d_in[2];
    const float* Wv = (const float*)d_in[3];
    float* out = (float*)d_out;

    qkv_proj_kernel<<<dim3(BATCH * SEQ / 64, 3), 256>>>(x, Wk, Wq, Wv);
    attn_kernel<<<BATCH * NQT * MAXCH, 256>>>();
    combine_kernel<<<BATCH * NQT, QROWS>>>(out);
}

// round 17
// speedup vs baseline: 1.6899x; 1.1143x over previous
#include <cuda_runtime.h>
#include <cuda_fp16.h>
#include <cstdint>

#define HEAD   64
#define SEQ    4096
#define BATCH  4
#define SCALE_LOG2E 0.18033688011112042f   // 0.125 * log2(e)
#define QROWS  64
#define NQT    (SEQ / QROWS)     // 64
#define KTILE  64
#define CHUNK  16                // kv tiles per CTA chunk
#define MAXCH  4

// ---------------------------------------------------------------------------
// Scratch
// ---------------------------------------------------------------------------
__device__ __align__(16) __half g_qh [BATCH * SEQ * HEAD];   // [b][t][c] *SCALE*log2e
__device__ __align__(16) __half g_kh [BATCH * SEQ * HEAD];   // [b][t][c]
__device__ __align__(16) __half g_vTh[BATCH * HEAD * SEQ];   // [b][c][t]
__device__ __align__(16) float g_Opart[BATCH * NQT * MAXCH * QROWS * HEAD];
__device__ __align__(16) float g_lpart[BATCH * NQT * MAXCH * QROWS];

// ---------------------------------------------------------------------------
// PTX helpers (generic sm_80+ only — target is plain sm_103)
// ---------------------------------------------------------------------------
__device__ __forceinline__ uint32_t smem_u32(const void* p) {
    uint32_t a;
    asm("{ .reg .u64 t; cvta.to.shared.u64 t, %1; cvt.u32.u64 %0, t; }"
        : "=r"(a) : "l"(p));
    return a;
}

#define LDSM4(r, addr) \
    asm volatile("ldmatrix.sync.aligned.m8n8.x4.shared.b16 {%0,%1,%2,%3}, [%4];" \
        : "=r"((r)[0]), "=r"((r)[1]), "=r"((r)[2]), "=r"((r)[3]) : "r"(addr))

#define MMA16816F16(d, a, b0, b1) \
    asm volatile("mma.sync.aligned.m16n8k16.row.col.f32.f16.f16.f32 " \
        "{%0,%1,%2,%3}, {%4,%5,%6,%7}, {%8,%9}, {%0,%1,%2,%3};" \
        : "+f"((d)[0]), "+f"((d)[1]), "+f"((d)[2]), "+f"((d)[3]) \
        : "r"((a)[0]), "r"((a)[1]), "r"((a)[2]), "r"((a)[3]), "r"(b0), "r"(b1))

#define CP_ASYNC16(smaddr, gptr) \
    asm volatile("cp.async.cg.shared.global [%0], [%1], 16;" \
        :: "r"(smaddr), "l"(gptr) : "memory")
#define CP_COMMIT() asm volatile("cp.async.commit_group;" ::: "memory")
#define CP_WAIT0()  asm volatile("cp.async.wait_group 0;"  ::: "memory")

__device__ __forceinline__ uint32_t pack_h2(float a, float b) {
    __half2 h = __floats2half2_rn(a, b);
    return *(uint32_t*)&h;
}
__device__ __forceinline__ float ex2f(float x) {
    float y; asm("ex2.approx.ftz.f32 %0, %1;" : "=f"(y) : "f"(x)); return y;
}

// ---------------------------------------------------------------------------
// Kernel 1: QKV projection on tensor cores (fp16 hi/lo 3-term, fp32 accum).
// (unchanged: measured 11.9-12.0us)
// ---------------------------------------------------------------------------
__global__ __launch_bounds__(256) void qkv_proj_kernel(
    const float* __restrict__ x,  const float* __restrict__ Wk,
    const float* __restrict__ Wq, const float* __restrict__ Wv)
{
    __shared__ __align__(16) uint8_t smx[2][64 * 144];   // x hi, lo
    __shared__ __align__(16) uint8_t smw[2][64 * 144];   // W hi, lo

    const int tid  = threadIdx.x;
    const int w    = tid >> 5;
    const int lane = tid & 31;
    const int row0 = blockIdx.x * 64;
    const int m    = blockIdx.y;

    const float* W = (m == 0) ? Wq : (m == 1) ? Wk : Wv;

    for (int i = tid; i < 64 * 16; i += 256) {
        int r = i >> 4, c4 = (i & 15) << 2;
        float4 v = *(const float4*)&x[(size_t)(row0 + r) * HEAD + c4];
        __half h0 = __float2half_rn(v.x), h1 = __float2half_rn(v.y);
        __half h2 = __float2half_rn(v.z), h3 = __float2half_rn(v.w);
        uint32_t off = (uint32_t)r * 144 + (uint32_t)c4 * 2;
        __half2 hh;
        hh.x = h0; hh.y = h1; *(uint32_t*)&smx[0][off]     = *(uint32_t*)&hh;
        hh.x = h2; hh.y = h3; *(uint32_t*)&smx[0][off + 4] = *(uint32_t*)&hh;
        hh.x = __float2half_rn(v.x - __half2float(h0));
        hh.y = __float2half_rn(v.y - __half2float(h1));
        *(uint32_t*)&smx[1][off]     = *(uint32_t*)&hh;
        hh.x = __float2half_rn(v.z - __half2float(h2));
        hh.y = __float2half_rn(v.w - __half2float(h3));
        *(uint32_t*)&smx[1][off + 4] = *(uint32_t*)&hh;
    }
    for (int i = tid; i < 64 * 16; i += 256) {
        int r = i >> 4, c4 = (i & 15) << 2;
        float4 v = *(const float4*)&W[(size_t)r * HEAD + c4];
        __half h0 = __float2half_rn(v.x), h1 = __float2half_rn(v.y);
        __half h2 = __float2half_rn(v.z), h3 = __float2half_rn(v.w);
        uint32_t off = (uint32_t)r * 144 + (uint32_t)c4 * 2;
        __half2 hh;
        hh.x = h0; hh.y = h1; *(uint32_t*)&smw[0][off]     = *(uint32_t*)&hh;
        hh.x = h2; hh.y = h3; *(uint32_t*)&smw[0][off + 4] = *(uint32_t*)&hh;
        hh.x = __float2half_rn(v.x - __half2float(h0));
        hh.y = __float2half_rn(v.y - __half2float(h1));
        *(uint32_t*)&smw[1][off]     = *(uint32_t*)&hh;
        hh.x = __float2half_rn(v.z - __half2float(h2));
        hh.y = __float2half_rn(v.w - __half2float(h3));
        *(uint32_t*)&smw[1][off + 4] = *(uint32_t*)&hh;
    }
    __syncthreads();

    uint32_t xh[4][4], xl[4][4];
    {
        const uint32_t base = (uint32_t)(16 * (w & 3) + (lane & 15)) * 144 + ((uint32_t)(lane >> 4) << 4);
        const uint32_t rah = smem_u32(&smx[0][0]) + base;
        const uint32_t ral = smem_u32(&smx[1][0]) + base;
        #pragma unroll
        for (int ks = 0; ks < 4; ks++) {
            LDSM4(xh[ks], rah + ks * 32);
            LDSM4(xl[ks], ral + ks * 32);
        }
    }

    float s[16];
    #pragma unroll
    for (int i = 0; i < 16; i++) s[i] = 0.f;

    #pragma unroll
    for (int ks = 0; ks < 4; ks++) {
        #pragma unroll
        for (int pr = 0; pr < 2; pr++) {
            const uint32_t a = smem_u32(&smw[0][0]) +
                (uint32_t)(32 * (w >> 2) + pr * 16 + (lane & 15)) * 144 +
                ((uint32_t)(lane >> 4) << 4) + ks * 32;
            uint32_t wh4[4], wl4[4];
            LDSM4(wh4, a);
            LDSM4(wl4, a + 9216);
            float* s0 = s + (2 * pr) * 4;
            float* s1 = s + (2 * pr + 1) * 4;
            MMA16816F16(s0, xh[ks], wh4[0], wh4[2]);
            MMA16816F16(s0, xh[ks], wl4[0], wl4[2]);
            MMA16816F16(s0, xl[ks], wh4[0], wh4[2]);
            MMA16816F16(s1, xh[ks], wh4[1], wh4[3]);
            MMA16816F16(s1, xh[ks], wl4[1], wl4[3]);
            MMA16816F16(s1, xl[ks], wh4[1], wh4[3]);
        }
    }

    const int b    = row0 / SEQ;
    const int r0   = 16 * (w & 3) + (lane >> 2);
    const int g0   = row0 + r0;
    const int g1   = g0 + 8;
    const int tv0  = g0 - b * SEQ;
    const int tv1  = tv0 + 8;
    const float sc = (m == 0) ? SCALE_LOG2E : 1.0f;

    #pragma unroll
    for (int nt = 0; nt < 4; nt++) {
        const int col = 32 * (w >> 2) + nt * 8 + 2 * (lane & 3);
        float a0 = s[nt * 4]     * sc, a1 = s[nt * 4 + 1] * sc;
        float a2 = s[nt * 4 + 2] * sc, a3 = s[nt * 4 + 3] * sc;
        if (m < 2) {
            __half* dst = (m == 0) ? g_qh : g_kh;
            *(uint32_t*)&dst[(size_t)g0 * HEAD + col] = pack_h2(a0, a1);
            *(uint32_t*)&dst[(size_t)g1 * HEAD + col] = pack_h2(a2, a3);
        } else {
            g_vTh[((size_t)b * HEAD + col)     * SEQ + tv0] = __float2half_rn(a0);
            g_vTh[((size_t)b * HEAD + col + 1) * SEQ + tv0] = __float2half_rn(a1);
            g_vTh[((size_t)b * HEAD + col)     * SEQ + tv1] = __float2half_rn(a2);
            g_vTh[((size_t)b * HEAD + col + 1) * SEQ + tv1] = __float2half_rn(a3);
        }
    }
}

// ---------------------------------------------------------------------------
// Kernel 2: fp16 mma.sync causal attention — SMALL CTA variant.
// 128 threads / 4 warps, QROWS=64, occ 4 (16 warps/SM in 4 independent CTAs:
// cheap 4-warp barriers, cross-CTA latency hiding). Same per-warp inner body
// as R14/R16. cp.async double-buffered, 1 sync/iter.
// ---------------------------------------------------------------------------
__global__ __launch_bounds__(128, 4) void attn_kernel()
{
    __shared__ __align__(16) uint8_t smB[2 * 18432];

    const int tid  = threadIdx.x;
    const int w    = tid >> 5;          // 0..3
    const int lane = tid & 31;

    const int bx = blockIdx.x;
    const int b  = bx & 3;
    const int qt = (NQT - 1) - ((bx >> 2) & 63);  // heavy tiles first
    const int ch = bx >> 8;

    const int ntiles = qt + 1;
    const int t0 = ch * CHUNK;
    const int t1 = (t0 + CHUNK < ntiles) ? (t0 + CHUNK) : ntiles;
    if (t0 >= t1) return;

    const uint32_t smb = smem_u32(smB);

    const __half* kbase = g_kh  + (size_t)b * SEQ * HEAD;
    const __half* vbase = g_vTh + (size_t)b * HEAD * SEQ;

    // issue one KV tile: 512 16B-segments per K and V, 128 threads -> 4+4 each
    auto issue_tile = [&](uint32_t tb, int tl) {
        const __half* kp = kbase + (size_t)tl * KTILE * HEAD;
        const __half* vp = vbase + (size_t)tl * KTILE;
        #pragma unroll
        for (int j = 0; j < 4; j++) {
            const int e  = tid + 128 * j;
            const int er = e >> 3, ec = e & 7;
            CP_ASYNC16(smb + tb + er * 144 + ec * 16,        kp + (size_t)er * HEAD + ec * 8);
            CP_ASYNC16(smb + tb + 9216 + er * 144 + ec * 16, vp + (size_t)er * SEQ  + ec * 8);
        }
        CP_COMMIT();
    };

    // ---- prologue: start tile t0 into buf0; stage Q (64 rows) into buf1 ----
    issue_tile(0, t0);
    {
        const __half* qh = g_qh + ((size_t)b * SEQ + (size_t)qt * QROWS) * HEAD;
        for (int i = tid; i < 64 * 8; i += 128) {
            int r = i >> 3, c = i & 7;
            *(uint4*)(smB + 18432 + r * 144 + c * 16) = *(const uint4*)(qh + r * HEAD + c * 8);
        }
    }
    __syncthreads();

    uint32_t qF[4][4];
    {
        const uint32_t ra = smb + 18432 + (uint32_t)(w * 16 + (lane & 15)) * 144 + ((lane >> 4) << 4);
        #pragma unroll
        for (int ks = 0; ks < 4; ks++) LDSM4(qF[ks], ra + ks * 32);
    }

    float o[32];
    #pragma unroll
    for (int i = 0; i < 32; i++) o[i] = 0.f;
    float l0 = 0.f, l1 = 0.f;

    const int row_in0 = w * 16 + (lane >> 2);        // 0..63
    const int grow0 = qt * QROWS + row_in0;
    const int grow1 = grow0 + 8;
    const uint32_t lrow  = (uint32_t)(lane & 15) * 144;
    const uint32_t lhalf = ((uint32_t)(lane >> 4)) << 4;

    for (int tl = t0; tl < t1; tl++) {
        const uint32_t cur = (uint32_t)((tl - t0) & 1) * 18432;
        const uint32_t nxt = cur ^ 18432;

        CP_WAIT0();
        __syncthreads();     // 4-warp barrier; covers Q LDSM on first iter

        if (tl + 1 < t1) issue_tile(nxt, tl + 1);

        // ---- S = Q K^T ----
        float s[32];
        #pragma unroll
        for (int i = 0; i < 32; i++) s[i] = 0.f;

        #pragma unroll
        for (int ks = 0; ks < 4; ks++) {
            #pragma unroll
            for (int pr = 0; pr < 4; pr++) {
                const uint32_t a = smb + cur + (uint32_t)(pr * 16) * 144 + lrow + lhalf + ks * 32;
                uint32_t k4[4];
                LDSM4(k4, a);
                MMA16816F16(s + (2 * pr) * 4,     qF[ks], k4[0], k4[2]);
                MMA16816F16(s + (2 * pr + 1) * 4, qF[ks], k4[1], k4[3]);
            }
        }

        // ---- softmax via ex2 (S carries log2e) ----
        const bool diag = (tl == qt);
        uint32_t pF[4][4];
        #pragma unroll
        for (int nt = 0; nt < 8; nt++) {
            const float* sp = s + nt * 4;
            float p0, p1, p2, p3;
            if (diag) {
                const int colb = tl * KTILE + nt * 8 + 2 * (lane & 3);
                p0 = (colb     <= grow0) ? ex2f(sp[0]) : 0.f;
                p1 = (colb + 1 <= grow0) ? ex2f(sp[1]) : 0.f;
                p2 = (colb     <= grow1) ? ex2f(sp[2]) : 0.f;
                p3 = (colb + 1 <= grow1) ? ex2f(sp[3]) : 0.f;
            } else {
                p0 = ex2f(sp[0]); p1 = ex2f(sp[1]);
                p2 = ex2f(sp[2]); p3 = ex2f(sp[3]);
            }
            l0 += p0 + p1;
            l1 += p2 + p3;
            const int ks  = nt >> 1;
            const int sel = (nt & 1) << 1;
            pF[ks][sel]     = pack_h2(p0, p1);
            pF[ks][sel + 1] = pack_h2(p2, p3);
        }

        // ---- O += P V ----
        #pragma unroll
        for (int ks = 0; ks < 4; ks++) {
            #pragma unroll
            for (int pr = 0; pr < 4; pr++) {
                const uint32_t a = smb + cur + 9216 + (uint32_t)(pr * 16) * 144 + lrow + lhalf + ks * 32;
                uint32_t v4[4];
                LDSM4(v4, a);
                MMA16816F16(o + (2 * pr) * 4,     pF[ks], v4[0], v4[2]);
                MMA16816F16(o + (2 * pr + 1) * 4, pF[ks], v4[1], v4[3]);
            }
        }
    }

    l0 += __shfl_xor_sync(0xffffffffu, l0, 1);
    l0 += __shfl_xor_sync(0xffffffffu, l0, 2);
    l1 += __shfl_xor_sync(0xffffffffu, l1, 1);
    l1 += __shfl_xor_sync(0xffffffffu, l1, 2);

    const size_t pb = ((size_t)(b * NQT + qt) * MAXCH + ch) * QROWS;
    const int c0 = 2 * (lane & 3);
    #pragma unroll
    for (int nt = 0; nt < 8; nt++) {
        float2 va = make_float2(o[nt * 4],     o[nt * 4 + 1]);
        float2 vb = make_float2(o[nt * 4 + 2], o[nt * 4 + 3]);
        *(float2*)&g_Opart[(pb + row_in0)     * HEAD + nt * 8 + c0] = va;
        *(float2*)&g_Opart[(pb + row_in0 + 8) * HEAD + nt * 8 + c0] = vb;
    }
    if ((lane & 3) == 0) {
        g_lpart[pb + row_in0]     = l0;
        g_lpart[pb + row_in0 + 8] = l1;
    }
}

// ---------------------------------------------------------------------------
// Kernel 3: combine split-KV partials (pure additive) + normalize.
// ---------------------------------------------------------------------------
__global__ __launch_bounds__(QROWS) void combine_kernel(float* __restrict__ out)
{
    const int b  = blockIdx.x & 3;
    const int qt = blockIdx.x >> 2;
    const int r  = threadIdx.x;
    const int nch = (qt + 1 + CHUNK - 1) / CHUNK;

    float acc[HEAD];
    #pragma unroll
    for (int i = 0; i < HEAD; i++) acc[i] = 0.0f;
    float l = 0.0f;

    for (int ch = 0; ch < nch; ch++) {
        const size_t base = (((size_t)(b * NQT + qt) * MAXCH + ch) * QROWS + r) * HEAD;
        const float4* op = (const float4*)(g_Opart + base);
        #pragma unroll
        for (int i = 0; i < 16; i++) {
            float4 v = op[i];
            acc[4 * i] += v.x; acc[4 * i + 1] += v.y;
            acc[4 * i + 2] += v.z; acc[4 * i + 3] += v.w;
        }
        l += g_lpart[((size_t)(b * NQT + qt) * MAXCH + ch) * QROWS + r];
    }

    const float inv = 1.0f / l;
    float4* dst = (float4*)(out + ((size_t)b * SEQ + (size_t)qt * QROWS + r) * HEAD);
    #pragma unroll
    for (int i = 0; i < 16; i++) {
        dst[i] = make_float4(acc[4 * i] * inv, acc[4 * i + 1] * inv,
                             acc[4 * i + 2] * inv, acc[4 * i + 3] * inv);
    }
}

// ---------------------------------------------------------------------------
extern "C" void kernel_launch(void* const* d_in, const int* in_sizes, int n_in,
                              void* d_out, int out_size)
{
    const float* x  = (const float*)d_in[0];
    const float* Wk = (const float*)d_in[1];
    const float* Wq = (const float*)d_in[2];
    const float* Wv = (const float*)d_in[3];
    float* out = (float*)d_out;

    qkv_proj_kernel<<<dim3(BATCH * SEQ / 64, 3), 256>>>(x, Wk, Wq, Wv);
    attn_kernel<<<BATCH * NQT * MAXCH, 128>>>();
    combine_kernel<<<BATCH * NQT, QROWS>>>(out);
}